// round 2
// baseline (speedup 1.0000x reference)
#include <cuda_runtime.h>
#include <cuda_bf16.h>
#include <stdint.h>

// Problem constants: N=100000 nodes, E=600000 edges, D=128.
#define N_MAX 100000
#define E_MAX 600000
#define DIM   128

// ---- device scratch (no cudaMalloc allowed) ----
__device__ int   g_deg[N_MAX];                     // in-degree per node
__device__ int   g_off[N_MAX + 1];                 // CSR row offsets (by dst)
__device__ int   g_cur[N_MAX];                     // scatter cursors
__device__ int   g_csr[E_MAX];                     // src node id per CSR slot
__device__ __align__(16) float g_agg[(size_t)N_MAX * DIM];  // mean-aggregated neighbors
__device__ __align__(16) float g_WT[256 * DIM];    // [Wl ; Wr] transposed

// ---------------------------------------------------------------------------
// 1) zero degree counters
__global__ void zero_deg_kernel(int n) {
    int i = blockIdx.x * blockDim.x + threadIdx.x;
    if (i < n) g_deg[i] = 0;
}

// 2) histogram of destination nodes (edge_index is int32: JAX default x64-off)
__global__ void hist_kernel(const int* __restrict__ ei, int E) {
    int i = blockIdx.x * blockDim.x + threadIdx.x;
    if (i < E) {
        int dst = ei[E + i];
        if (dst >= 0 && dst < N_MAX) atomicAdd(&g_deg[dst], 1);
    }
}

// 3) single-block exclusive scan over g_deg -> g_off, g_cur; g_off[n] = E
__global__ void scan_kernel(int n) {
    __shared__ int s[1024];
    int t = threadIdx.x;
    int seg = (n + 1023) / 1024;
    int start = t * seg;
    int end = start + seg; if (end > n) end = n;
    if (start > n) start = n;

    int sum = 0;
    for (int i = start; i < end; ++i) sum += g_deg[i];
    s[t] = sum;
    __syncthreads();

    for (int off = 1; off < 1024; off <<= 1) {
        int tmp = 0;
        if (t >= off) tmp = s[t - off];
        __syncthreads();
        s[t] += tmp;
        __syncthreads();
    }

    int running = s[t] - sum;   // exclusive prefix for this thread's segment
    for (int i = start; i < end; ++i) {
        g_off[i] = running;
        g_cur[i] = running;
        running += g_deg[i];
    }
    if (t == 1023) g_off[n] = s[1023];
}

// 4) scatter src ids into CSR slots
__global__ void scatter_kernel(const int* __restrict__ ei, int E) {
    int i = blockIdx.x * blockDim.x + threadIdx.x;
    if (i < E) {
        int src = ei[i];
        int dst = ei[E + i];
        if (dst >= 0 && dst < N_MAX) {
            int pos = atomicAdd(&g_cur[dst], 1);
            if (pos >= 0 && pos < E_MAX) g_csr[pos] = src;
        }
    }
}

// 5) transpose [W_l ; W_r] into g_WT: g_WT[k*128 + j]
__global__ void transpose_w_kernel(const float* __restrict__ Wl,
                                   const float* __restrict__ Wr) {
    int idx = blockIdx.x * blockDim.x + threadIdx.x;   // 0 .. 256*128-1
    if (idx >= 256 * DIM) return;
    int k = idx >> 7;
    int j = idx & 127;
    g_WT[idx] = (k < DIM) ? Wl[j * DIM + k] : Wr[j * DIM + (k - DIM)];
}

// 6) mean aggregation: one warp per node, lane owns 4 contiguous floats
__global__ void agg_kernel(const float* __restrict__ feat, int n) {
    int gwarp = (blockIdx.x * blockDim.x + threadIdx.x) >> 5;
    int lane = threadIdx.x & 31;
    if (gwarp >= n) return;

    int beg = g_off[gwarp];
    int end = g_off[gwarp + 1];
    float4 acc = make_float4(0.f, 0.f, 0.f, 0.f);
    for (int e = beg; e < end; ++e) {
        int s = g_csr[e];                 // same addr across warp -> broadcast
        float4 v = *(const float4*)&feat[(size_t)s * DIM + lane * 4];
        acc.x += v.x; acc.y += v.y; acc.z += v.z; acc.w += v.w;
    }
    int d = end - beg;
    float scale = 1.0f / (float)(d > 0 ? d : 1);
    acc.x *= scale; acc.y *= scale; acc.z *= scale; acc.w *= scale;
    *(float4*)&g_agg[(size_t)gwarp * DIM + lane * 4] = acc;
}

// 7) fused GEMM: out[N,128] = [agg | feat](N,256) x g_WT(256,128) + b_l
//    BM=64 rows/block, BN=128 (all cols), BK=16; 256 threads, 8x4 micro-tile.
#define BM 64
#define BK 16
__global__ __launch_bounds__(256)
void gemm_kernel(const float* __restrict__ feat,
                 const float* __restrict__ b_l,
                 float* __restrict__ out, int n) {
    __shared__ float As[BM][BK + 1];
    __shared__ float Bs[BK][DIM];

    int tid = threadIdx.x;
    int tx = tid & 31;      // column group: col = tx*4
    int ty = tid >> 5;      // row group: rows ty*8 .. ty*8+7
    int col = tx * 4;
    int block_row = blockIdx.x * BM;

    float4 bb = *(const float4*)&b_l[col];
    float acc[8][4];
#pragma unroll
    for (int r = 0; r < 8; ++r) {
        acc[r][0] = bb.x; acc[r][1] = bb.y; acc[r][2] = bb.z; acc[r][3] = bb.w;
    }

    // A-tile load mapping: thread -> (row = tid>>2, 4 cols at (tid&3)*4)
    int a_row = tid >> 2;
    int a_cc = (tid & 3) * 4;

    for (int k0 = 0; k0 < 256; k0 += BK) {
        const float* Asrc = (k0 < DIM) ? g_agg : feat;
        int ksrc = (k0 < DIM) ? k0 : (k0 - DIM);

        // load A tile (64x16)
        {
            int grow = block_row + a_row;
            float4 v = make_float4(0.f, 0.f, 0.f, 0.f);
            if (grow < n)
                v = *(const float4*)&Asrc[(size_t)grow * DIM + ksrc + a_cc];
            As[a_row][a_cc + 0] = v.x;
            As[a_row][a_cc + 1] = v.y;
            As[a_row][a_cc + 2] = v.z;
            As[a_row][a_cc + 3] = v.w;
        }
        // load B tile (16x128) from pre-transposed g_WT — coalesced float4
        {
#pragma unroll
            for (int it = 0; it < 2; ++it) {
                int idx4 = tid + it * 256;        // 0..511
                int brow = idx4 >> 5;             // 16 rows
                int bc = (idx4 & 31) * 4;         // 128 cols
                float4 v = *(const float4*)&g_WT[(size_t)(k0 + brow) * DIM + bc];
                *(float4*)&Bs[brow][bc] = v;
            }
        }
        __syncthreads();

#pragma unroll
        for (int kk = 0; kk < BK; ++kk) {
            float4 b = *(const float4*)&Bs[kk][col];
#pragma unroll
            for (int r = 0; r < 8; ++r) {
                float a = As[ty * 8 + r][kk];     // warp-uniform broadcast
                acc[r][0] += a * b.x;
                acc[r][1] += a * b.y;
                acc[r][2] += a * b.z;
                acc[r][3] += a * b.w;
            }
        }
        __syncthreads();
    }

#pragma unroll
    for (int r = 0; r < 8; ++r) {
        int grow = block_row + ty * 8 + r;
        if (grow < n) {
            float4 v = make_float4(acc[r][0], acc[r][1], acc[r][2], acc[r][3]);
            *(float4*)&out[(size_t)grow * DIM + col] = v;
        }
    }
}

extern "C" void kernel_launch(void* const* d_in, const int* in_sizes, int n_in,
                              void* d_out, int out_size) {
    const float* feature = (const float*)d_in[0];
    const int*   ei      = (const int*)d_in[1];     // int32 (JAX x64 disabled)
    const float* W_l     = (const float*)d_in[2];
    const float* b_l     = (const float*)d_in[3];
    const float* W_r     = (const float*)d_in[4];
    float*       out     = (float*)d_out;

    int N = in_sizes[0] / DIM;
    int E = in_sizes[1] / 2;

    // independent: transpose weights
    transpose_w_kernel<<<(256 * DIM + 255) / 256, 256>>>(W_l, W_r);

    // CSR build
    zero_deg_kernel<<<(N + 255) / 256, 256>>>(N);
    hist_kernel<<<(E + 255) / 256, 256>>>(ei, E);
    scan_kernel<<<1, 1024>>>(N);
    scatter_kernel<<<(E + 255) / 256, 256>>>(ei, E);

    // mean aggregation: one warp per node, 8 warps per block
    int agg_blocks = (N + 7) / 8;
    agg_kernel<<<agg_blocks, 256>>>(feature, N);

    // fused linear layers
    gemm_kernel<<<(N + BM - 1) / BM, 256>>>(feature, b_l, out, N);
}

// round 3
// speedup vs baseline: 1.6294x; 1.6294x over previous
#include <cuda_runtime.h>
#include <cuda_bf16.h>
#include <stdint.h>

// Problem constants: N=100000 nodes, E=600000 edges, D=128.
#define N_MAX 100000
#define E_MAX 600000
#define DIM   128

// multi-block scan geometry
#define SC_BLK   256
#define SC_PER   8
#define SC_CHUNK (SC_BLK * SC_PER)            // 2048
#define SC_NBLK  ((N_MAX + SC_CHUNK - 1) / SC_CHUNK)   // 49

// ---- device scratch (no cudaMalloc allowed) ----
__device__ int   g_deg[N_MAX];                     // in-degree per node
__device__ int   g_off[N_MAX + 1];                 // CSR row offsets (by dst)
__device__ int   g_cur[N_MAX];                     // scatter cursors
__device__ int   g_csr[E_MAX];                     // src node id per CSR slot
__device__ int   g_part[SC_NBLK + 1];              // per-chunk partial sums / prefixes
__device__ __align__(16) float g_agg[(size_t)N_MAX * DIM];  // mean-aggregated neighbors
__device__ __align__(16) float g_WT[256 * DIM];    // [Wl ; Wr] transposed

// ---------------------------------------------------------------------------
// 1) zero degree counters
__global__ void zero_deg_kernel(int n) {
    int i = blockIdx.x * blockDim.x + threadIdx.x;
    if (i < n) g_deg[i] = 0;
}

// 2) histogram of destination nodes (edge_index is int32)
__global__ void hist_kernel(const int* __restrict__ ei, int E) {
    int i = blockIdx.x * blockDim.x + threadIdx.x;
    if (i < E) {
        int dst = ei[E + i];
        if (dst >= 0 && dst < N_MAX) atomicAdd(&g_deg[dst], 1);
    }
}

// 3a) per-chunk partial sums: block b reduces g_deg[b*2048 .. b*2048+2047]
__global__ void part_sum_kernel(int n) {
    __shared__ int s[SC_BLK];
    int t = threadIdx.x;
    int base = blockIdx.x * SC_CHUNK + t * SC_PER;
    int sum = 0;
#pragma unroll
    for (int j = 0; j < SC_PER; ++j) {
        int i = base + j;
        if (i < n) sum += g_deg[i];
    }
    s[t] = sum;
    __syncthreads();
#pragma unroll
    for (int off = SC_BLK / 2; off > 0; off >>= 1) {
        if (t < off) s[t] += s[t + off];
        __syncthreads();
    }
    if (t == 0) g_part[blockIdx.x] = s[0];
}

// 3b) scan the (<=64) chunk partials into exclusive prefixes
__global__ void part_scan_kernel(int nblocks) {
    __shared__ int s[64];
    int t = threadIdx.x;
    int v = (t < nblocks) ? g_part[t] : 0;
    s[t] = v;
    __syncthreads();
#pragma unroll
    for (int off = 1; off < 64; off <<= 1) {
        int tmp = (t >= off) ? s[t - off] : 0;
        __syncthreads();
        s[t] += tmp;
        __syncthreads();
    }
    if (t < nblocks) g_part[t] = s[t] - v;   // exclusive prefix
}

// 3c) write offsets: each block re-scans its chunk with the chunk prefix
__global__ void off_kernel(int n, int E) {
    __shared__ int s[SC_BLK];
    int t = threadIdx.x;
    int base = blockIdx.x * SC_CHUNK + t * SC_PER;
    int v[SC_PER];
    int sum = 0;
#pragma unroll
    for (int j = 0; j < SC_PER; ++j) {
        int i = base + j;
        v[j] = (i < n) ? g_deg[i] : 0;
        sum += v[j];
    }
    s[t] = sum;
    __syncthreads();
#pragma unroll
    for (int off = 1; off < SC_BLK; off <<= 1) {
        int tmp = (t >= off) ? s[t - off] : 0;
        __syncthreads();
        s[t] += tmp;
        __syncthreads();
    }
    int run = g_part[blockIdx.x] + s[t] - sum;   // exclusive prefix for this thread
#pragma unroll
    for (int j = 0; j < SC_PER; ++j) {
        int i = base + j;
        if (i < n) {
            g_off[i] = run;
            g_cur[i] = run;
            run += v[j];
        }
    }
    if (blockIdx.x == 0 && t == 0) g_off[n] = E;
}

// 4) scatter src ids into CSR slots
__global__ void scatter_kernel(const int* __restrict__ ei, int E) {
    int i = blockIdx.x * blockDim.x + threadIdx.x;
    if (i < E) {
        int src = ei[i];
        int dst = ei[E + i];
        if (dst >= 0 && dst < N_MAX) {
            int pos = atomicAdd(&g_cur[dst], 1);
            if (pos >= 0 && pos < E_MAX) g_csr[pos] = src;
        }
    }
}

// 5) transpose [W_l ; W_r] into g_WT: g_WT[k*128 + j]
__global__ void transpose_w_kernel(const float* __restrict__ Wl,
                                   const float* __restrict__ Wr) {
    int idx = blockIdx.x * blockDim.x + threadIdx.x;   // 0 .. 256*128-1
    if (idx >= 256 * DIM) return;
    int k = idx >> 7;
    int j = idx & 127;
    g_WT[idx] = (k < DIM) ? Wl[j * DIM + k] : Wr[j * DIM + (k - DIM)];
}

// 6) mean aggregation: one warp per node, lane owns 4 contiguous floats
__global__ void agg_kernel(const float* __restrict__ feat, int n) {
    int gwarp = (blockIdx.x * blockDim.x + threadIdx.x) >> 5;
    int lane = threadIdx.x & 31;
    if (gwarp >= n) return;

    int beg = g_off[gwarp];
    int end = g_off[gwarp + 1];
    float4 acc = make_float4(0.f, 0.f, 0.f, 0.f);
    for (int e = beg; e < end; ++e) {
        int s = g_csr[e];                 // same addr across warp -> broadcast
        float4 v = *(const float4*)&feat[(size_t)s * DIM + lane * 4];
        acc.x += v.x; acc.y += v.y; acc.z += v.z; acc.w += v.w;
    }
    int d = end - beg;
    float scale = 1.0f / (float)(d > 0 ? d : 1);
    acc.x *= scale; acc.y *= scale; acc.z *= scale; acc.w *= scale;
    *(float4*)&g_agg[(size_t)gwarp * DIM + lane * 4] = acc;
}

// 7) fused GEMM: out[N,128] = [agg | feat](N,256) x g_WT(256,128) + b_l
#define BM 64
#define BK 16
__global__ __launch_bounds__(256)
void gemm_kernel(const float* __restrict__ feat,
                 const float* __restrict__ b_l,
                 float* __restrict__ out, int n) {
    __shared__ float As[BM][BK + 1];
    __shared__ float Bs[BK][DIM];

    int tid = threadIdx.x;
    int tx = tid & 31;      // column group: col = tx*4
    int ty = tid >> 5;      // row group: rows ty*8 .. ty*8+7
    int col = tx * 4;
    int block_row = blockIdx.x * BM;

    float4 bb = *(const float4*)&b_l[col];
    float acc[8][4];
#pragma unroll
    for (int r = 0; r < 8; ++r) {
        acc[r][0] = bb.x; acc[r][1] = bb.y; acc[r][2] = bb.z; acc[r][3] = bb.w;
    }

    int a_row = tid >> 2;
    int a_cc = (tid & 3) * 4;

    for (int k0 = 0; k0 < 256; k0 += BK) {
        const float* Asrc = (k0 < DIM) ? g_agg : feat;
        int ksrc = (k0 < DIM) ? k0 : (k0 - DIM);

        {   // load A tile (64x16)
            int grow = block_row + a_row;
            float4 v = make_float4(0.f, 0.f, 0.f, 0.f);
            if (grow < n)
                v = *(const float4*)&Asrc[(size_t)grow * DIM + ksrc + a_cc];
            As[a_row][a_cc + 0] = v.x;
            As[a_row][a_cc + 1] = v.y;
            As[a_row][a_cc + 2] = v.z;
            As[a_row][a_cc + 3] = v.w;
        }
        {   // load B tile (16x128)
#pragma unroll
            for (int it = 0; it < 2; ++it) {
                int idx4 = tid + it * 256;
                int brow = idx4 >> 5;
                int bc = (idx4 & 31) * 4;
                float4 v = *(const float4*)&g_WT[(size_t)(k0 + brow) * DIM + bc];
                *(float4*)&Bs[brow][bc] = v;
            }
        }
        __syncthreads();

#pragma unroll
        for (int kk = 0; kk < BK; ++kk) {
            float4 b = *(const float4*)&Bs[kk][col];
#pragma unroll
            for (int r = 0; r < 8; ++r) {
                float a = As[ty * 8 + r][kk];
                acc[r][0] += a * b.x;
                acc[r][1] += a * b.y;
                acc[r][2] += a * b.z;
                acc[r][3] += a * b.w;
            }
        }
        __syncthreads();
    }

#pragma unroll
    for (int r = 0; r < 8; ++r) {
        int grow = block_row + ty * 8 + r;
        if (grow < n) {
            float4 v = make_float4(acc[r][0], acc[r][1], acc[r][2], acc[r][3]);
            *(float4*)&out[(size_t)grow * DIM + col] = v;
        }
    }
}

extern "C" void kernel_launch(void* const* d_in, const int* in_sizes, int n_in,
                              void* d_out, int out_size) {
    const float* feature = (const float*)d_in[0];
    const int*   ei      = (const int*)d_in[1];     // int32 (JAX x64 disabled)
    const float* W_l     = (const float*)d_in[2];
    const float* b_l     = (const float*)d_in[3];
    const float* W_r     = (const float*)d_in[4];
    float*       out     = (float*)d_out;

    int N = in_sizes[0] / DIM;
    int E = in_sizes[1] / 2;

    // independent: transpose weights
    transpose_w_kernel<<<(256 * DIM + 255) / 256, 256>>>(W_l, W_r);

    // CSR build
    zero_deg_kernel<<<(N + 255) / 256, 256>>>(N);
    hist_kernel<<<(E + 255) / 256, 256>>>(ei, E);

    int nblk = (N + SC_CHUNK - 1) / SC_CHUNK;   // 49 for N=100000
    part_sum_kernel<<<nblk, SC_BLK>>>(N);
    part_scan_kernel<<<1, 64>>>(nblk);
    off_kernel<<<nblk, SC_BLK>>>(N, E);

    scatter_kernel<<<(E + 255) / 256, 256>>>(ei, E);

    // mean aggregation: one warp per node, 8 warps per block
    int agg_blocks = (N + 7) / 8;
    agg_kernel<<<agg_blocks, 256>>>(feature, N);

    // fused linear layers
    gemm_kernel<<<(N + BM - 1) / BM, 256>>>(feature, b_l, out, N);
}

// round 4
// speedup vs baseline: 2.5153x; 1.5437x over previous
#include <cuda_runtime.h>
#include <cuda_bf16.h>
#include <stdint.h>

// Problem constants: N=100000 nodes, E=600000 edges, D=128.
#define N_MAX 100000
#define E_MAX 600000
#define DIM   128

// multi-block scan geometry
#define SC_BLK   256
#define SC_PER   8
#define SC_CHUNK (SC_BLK * SC_PER)            // 2048
#define SC_NBLK  ((N_MAX + SC_CHUNK - 1) / SC_CHUNK)   // 49

// ---- device scratch (no cudaMalloc allowed) ----
__device__ int   g_deg[N_MAX];
__device__ int   g_off[N_MAX + 1];
__device__ int   g_cur[N_MAX];
__device__ int   g_csr[E_MAX];
__device__ int   g_part[SC_NBLK + 1];
__device__ __align__(16) float g_agg[(size_t)N_MAX * DIM];
__device__ __align__(16) float g_WT[256 * DIM];   // [Wl ; Wr]^T, tf32-rounded

// ---------------------------------------------------------------------------
__global__ void zero_deg_kernel(int n) {
    int i = blockIdx.x * blockDim.x + threadIdx.x;
    if (i < n) g_deg[i] = 0;
}

__global__ void hist_kernel(const int* __restrict__ ei, int E) {
    int i = blockIdx.x * blockDim.x + threadIdx.x;
    if (i < E) {
        int dst = ei[E + i];
        if (dst >= 0 && dst < N_MAX) atomicAdd(&g_deg[dst], 1);
    }
}

__global__ void part_sum_kernel(int n) {
    __shared__ int s[SC_BLK];
    int t = threadIdx.x;
    int base = blockIdx.x * SC_CHUNK + t * SC_PER;
    int sum = 0;
#pragma unroll
    for (int j = 0; j < SC_PER; ++j) {
        int i = base + j;
        if (i < n) sum += g_deg[i];
    }
    s[t] = sum;
    __syncthreads();
#pragma unroll
    for (int off = SC_BLK / 2; off > 0; off >>= 1) {
        if (t < off) s[t] += s[t + off];
        __syncthreads();
    }
    if (t == 0) g_part[blockIdx.x] = s[0];
}

__global__ void part_scan_kernel(int nblocks) {
    __shared__ int s[64];
    int t = threadIdx.x;
    int v = (t < nblocks) ? g_part[t] : 0;
    s[t] = v;
    __syncthreads();
#pragma unroll
    for (int off = 1; off < 64; off <<= 1) {
        int tmp = (t >= off) ? s[t - off] : 0;
        __syncthreads();
        s[t] += tmp;
        __syncthreads();
    }
    if (t < nblocks) g_part[t] = s[t] - v;
}

__global__ void off_kernel(int n, int E) {
    __shared__ int s[SC_BLK];
    int t = threadIdx.x;
    int base = blockIdx.x * SC_CHUNK + t * SC_PER;
    int v[SC_PER];
    int sum = 0;
#pragma unroll
    for (int j = 0; j < SC_PER; ++j) {
        int i = base + j;
        v[j] = (i < n) ? g_deg[i] : 0;
        sum += v[j];
    }
    s[t] = sum;
    __syncthreads();
#pragma unroll
    for (int off = 1; off < SC_BLK; off <<= 1) {
        int tmp = (t >= off) ? s[t - off] : 0;
        __syncthreads();
        s[t] += tmp;
        __syncthreads();
    }
    int run = g_part[blockIdx.x] + s[t] - sum;
#pragma unroll
    for (int j = 0; j < SC_PER; ++j) {
        int i = base + j;
        if (i < n) {
            g_off[i] = run;
            g_cur[i] = run;
            run += v[j];
        }
    }
    if (blockIdx.x == 0 && t == 0) g_off[n] = E;
}

__global__ void scatter_kernel(const int* __restrict__ ei, int E) {
    int i = blockIdx.x * blockDim.x + threadIdx.x;
    if (i < E) {
        int src = ei[i];
        int dst = ei[E + i];
        if (dst >= 0 && dst < N_MAX) {
            int pos = atomicAdd(&g_cur[dst], 1);
            if (pos >= 0 && pos < E_MAX) g_csr[pos] = src;
        }
    }
}

__device__ __forceinline__ float to_tf32(float x) {
    float y;
    asm("cvt.rna.tf32.f32 %0, %1;" : "=f"(y) : "f"(x));
    return y;
}

// transpose [W_l ; W_r] into g_WT (tf32-rounded): g_WT[k*128 + j]
__global__ void transpose_w_kernel(const float* __restrict__ Wl,
                                   const float* __restrict__ Wr) {
    int idx = blockIdx.x * blockDim.x + threadIdx.x;
    if (idx >= 256 * DIM) return;
    int k = idx >> 7;
    int j = idx & 127;
    float v = (k < DIM) ? Wl[j * DIM + k] : Wr[j * DIM + (k - DIM)];
    g_WT[idx] = to_tf32(v);
}

// mean aggregation: one warp per node
__global__ void agg_kernel(const float* __restrict__ feat, int n) {
    int gwarp = (blockIdx.x * blockDim.x + threadIdx.x) >> 5;
    int lane = threadIdx.x & 31;
    if (gwarp >= n) return;

    int beg = g_off[gwarp];
    int end = g_off[gwarp + 1];
    float4 acc = make_float4(0.f, 0.f, 0.f, 0.f);
    for (int e = beg; e < end; ++e) {
        int s = g_csr[e];
        float4 v = *(const float4*)&feat[(size_t)s * DIM + lane * 4];
        acc.x += v.x; acc.y += v.y; acc.z += v.z; acc.w += v.w;
    }
    int d = end - beg;
    float scale = 1.0f / (float)(d > 0 ? d : 1);
    acc.x *= scale; acc.y *= scale; acc.z *= scale; acc.w *= scale;
    *(float4*)&g_agg[(size_t)gwarp * DIM + lane * 4] = acc;
}

// ---------------------------------------------------------------------------
// tf32 tensor-core GEMM: out[N,128] = [agg | feat](N,256) x g_WT(256,128) + b_l
// Block tile 128x128, 8 warps (4x2), warp tile 32x64, mma.m16n8k8.
#define GBM 128
#define GKB 32
#define AS_STRIDE 36   // banks (4g+t): conflict-free A frag loads
#define BS_STRIDE 136  // banks (8t+g): conflict-free B frag loads

__global__ __launch_bounds__(256)
void gemm_tc_kernel(const float* __restrict__ feat,
                    const float* __restrict__ b_l,
                    float* __restrict__ out, int n) {
    __shared__ float As[GBM * AS_STRIDE];   // 128 x 32 (padded)
    __shared__ float Bs[GKB * BS_STRIDE];   // 32 x 128 (padded)

    int tid = threadIdx.x;
    int wid = tid >> 5;
    int lane = tid & 31;
    int g = lane >> 2, t = lane & 3;

    int wr = wid & 3;           // warp row: rows wr*32 .. +31
    int wc = wid >> 2;          // warp col: cols wc*64 .. +63
    int block_row = blockIdx.x * GBM;

    // bias preload (per nt, cols 2t / 2t+1)
    float bias0[8], bias1[8];
#pragma unroll
    for (int nt = 0; nt < 8; ++nt) {
        int c = wc * 64 + nt * 8 + 2 * t;
        bias0[nt] = b_l[c];
        bias1[nt] = b_l[c + 1];
    }

    float acc[2][8][4];
#pragma unroll
    for (int mt = 0; mt < 2; ++mt)
#pragma unroll
        for (int nt = 0; nt < 8; ++nt) {
            acc[mt][nt][0] = bias0[nt];
            acc[mt][nt][1] = bias1[nt];
            acc[mt][nt][2] = bias0[nt];
            acc[mt][nt][3] = bias1[nt];
        }

#pragma unroll 1
    for (int kc = 0; kc < 8; ++kc) {
        const float* Asrc = (kc < 4) ? g_agg : feat;
        int ksrc = (kc * GKB) & 127;

        // load A tile 128x32 (1024 float4, 4 per thread), cvt to tf32
#pragma unroll
        for (int i = 0; i < 4; ++i) {
            int idx4 = tid + i * 256;
            int row = idx4 >> 3;
            int c4 = (idx4 & 7) * 4;
            int grow = block_row + row;
            float4 v = make_float4(0.f, 0.f, 0.f, 0.f);
            if (grow < n)
                v = *(const float4*)&Asrc[(size_t)grow * DIM + ksrc + c4];
            float* dst = &As[row * AS_STRIDE + c4];
            dst[0] = to_tf32(v.x);
            dst[1] = to_tf32(v.y);
            dst[2] = to_tf32(v.z);
            dst[3] = to_tf32(v.w);
        }
        // load B tile 32x128 (already tf32-rounded)
#pragma unroll
        for (int i = 0; i < 4; ++i) {
            int idx4 = tid + i * 256;
            int brow = idx4 >> 5;
            int bc = (idx4 & 31) * 4;
            float4 v = *(const float4*)&g_WT[(size_t)(kc * GKB + brow) * DIM + bc];
            *(float4*)&Bs[brow * BS_STRIDE + bc] = v;
        }
        __syncthreads();

#pragma unroll
        for (int ks = 0; ks < 4; ++ks) {
            int kb = ks * 8;
            uint32_t a[2][4];
#pragma unroll
            for (int mt = 0; mt < 2; ++mt) {
                int rb = wr * 32 + mt * 16;
                a[mt][0] = __float_as_uint(As[(rb + g) * AS_STRIDE + kb + t]);
                a[mt][1] = __float_as_uint(As[(rb + g + 8) * AS_STRIDE + kb + t]);
                a[mt][2] = __float_as_uint(As[(rb + g) * AS_STRIDE + kb + t + 4]);
                a[mt][3] = __float_as_uint(As[(rb + g + 8) * AS_STRIDE + kb + t + 4]);
            }
#pragma unroll
            for (int nt = 0; nt < 8; ++nt) {
                int cb = wc * 64 + nt * 8 + g;
                uint32_t b0 = __float_as_uint(Bs[(kb + t) * BS_STRIDE + cb]);
                uint32_t b1 = __float_as_uint(Bs[(kb + t + 4) * BS_STRIDE + cb]);
#pragma unroll
                for (int mt = 0; mt < 2; ++mt) {
                    asm volatile(
                        "mma.sync.aligned.m16n8k8.row.col.f32.tf32.tf32.f32 "
                        "{%0,%1,%2,%3}, {%4,%5,%6,%7}, {%8,%9}, {%0,%1,%2,%3};"
                        : "+f"(acc[mt][nt][0]), "+f"(acc[mt][nt][1]),
                          "+f"(acc[mt][nt][2]), "+f"(acc[mt][nt][3])
                        : "r"(a[mt][0]), "r"(a[mt][1]), "r"(a[mt][2]), "r"(a[mt][3]),
                          "r"(b0), "r"(b1));
                }
            }
        }
        __syncthreads();
    }

    // epilogue: write 2-float pairs per fragment register pair
#pragma unroll
    for (int mt = 0; mt < 2; ++mt) {
        int r0 = block_row + wr * 32 + mt * 16 + g;
        int r1 = r0 + 8;
#pragma unroll
        for (int nt = 0; nt < 8; ++nt) {
            int c = wc * 64 + nt * 8 + 2 * t;
            if (r0 < n) {
                float2 v = make_float2(acc[mt][nt][0], acc[mt][nt][1]);
                *(float2*)&out[(size_t)r0 * DIM + c] = v;
            }
            if (r1 < n) {
                float2 v = make_float2(acc[mt][nt][2], acc[mt][nt][3]);
                *(float2*)&out[(size_t)r1 * DIM + c] = v;
            }
        }
    }
}

extern "C" void kernel_launch(void* const* d_in, const int* in_sizes, int n_in,
                              void* d_out, int out_size) {
    const float* feature = (const float*)d_in[0];
    const int*   ei      = (const int*)d_in[1];     // int32 (JAX x64 disabled)
    const float* W_l     = (const float*)d_in[2];
    const float* b_l     = (const float*)d_in[3];
    const float* W_r     = (const float*)d_in[4];
    float*       out     = (float*)d_out;

    int N = in_sizes[0] / DIM;
    int E = in_sizes[1] / 2;

    transpose_w_kernel<<<(256 * DIM + 255) / 256, 256>>>(W_l, W_r);

    zero_deg_kernel<<<(N + 255) / 256, 256>>>(N);
    hist_kernel<<<(E + 255) / 256, 256>>>(ei, E);

    int nblk = (N + SC_CHUNK - 1) / SC_CHUNK;
    part_sum_kernel<<<nblk, SC_BLK>>>(N);
    part_scan_kernel<<<1, 64>>>(nblk);
    off_kernel<<<nblk, SC_BLK>>>(N, E);

    scatter_kernel<<<(E + 255) / 256, 256>>>(ei, E);

    int agg_blocks = (N + 7) / 8;
    agg_kernel<<<agg_blocks, 256>>>(feature, N);

    gemm_tc_kernel<<<(N + GBM - 1) / GBM, 256>>>(feature, b_l, out, N);
}

// round 5
// speedup vs baseline: 3.2948x; 1.3099x over previous
#include <cuda_runtime.h>
#include <cuda_bf16.h>
#include <stdint.h>

// Problem constants: N=100000 nodes, E=600000 edges, D=128.
#define N_MAX 100000
#define E_MAX 600000
#define DIM   128

// multi-block scan geometry
#define SC_BLK   256
#define SC_PER   8
#define SC_CHUNK (SC_BLK * SC_PER)            // 2048
#define SC_NBLK  ((N_MAX + SC_CHUNK - 1) / SC_CHUNK)   // 49 (must be <= 64)

// ---- device scratch (no cudaMalloc allowed) ----
__device__ int   g_deg[N_MAX];
__device__ int   g_off[N_MAX + 1];
__device__ int   g_cur[N_MAX];
__device__ int   g_csr[E_MAX];
__device__ int   g_part[64];
__device__ __align__(16) float g_agg[(size_t)N_MAX * DIM];  // tf32-rounded means
__device__ __align__(16) float g_WT[256 * DIM];             // [Wl ; Wr]^T tf32

__device__ __forceinline__ float to_tf32(float x) {
    float y;
    asm("cvt.rna.tf32.f32 %0, %1;" : "=f"(y) : "f"(x));
    return y;
}

// ---------------------------------------------------------------------------
// 0) merged init: zero degree counters + transpose/round weights
__global__ void init_kernel(const float* __restrict__ Wl,
                            const float* __restrict__ Wr, int n) {
    int i = blockIdx.x * blockDim.x + threadIdx.x;
    if (i < n) g_deg[i] = 0;
    if (i < 256 * DIM) {
        int k = i >> 7;
        int j = i & 127;
        float v = (k < DIM) ? Wl[j * DIM + k] : Wr[j * DIM + (k - DIM)];
        g_WT[i] = to_tf32(v);
    }
}

// 1) histogram of destination nodes (edge_index is int32)
__global__ void hist_kernel(const int* __restrict__ ei, int E) {
    int i = blockIdx.x * blockDim.x + threadIdx.x;
    if (i < E) {
        int dst = ei[E + i];
        if (dst >= 0 && dst < N_MAX) atomicAdd(&g_deg[dst], 1);
    }
}

// 2) per-chunk partial sums
__global__ void part_sum_kernel(int n) {
    __shared__ int s[SC_BLK];
    int t = threadIdx.x;
    int base = blockIdx.x * SC_CHUNK + t * SC_PER;
    int sum = 0;
#pragma unroll
    for (int j = 0; j < SC_PER; ++j) {
        int i = base + j;
        if (i < n) sum += g_deg[i];
    }
    s[t] = sum;
    __syncthreads();
#pragma unroll
    for (int off = SC_BLK / 2; off > 0; off >>= 1) {
        if (t < off) s[t] += s[t + off];
        __syncthreads();
    }
    if (t == 0) g_part[blockIdx.x] = s[0];
}

// 3) offsets: each block scans the (<=64) chunk partials itself, then re-scans
//    its own 2048-element chunk and writes g_off / g_cur.
__global__ void off_kernel(int n, int E, int nblk) {
    __shared__ int sp[64];
    __shared__ int s[SC_BLK];
    int t = threadIdx.x;

    if (t < 64) sp[t] = (t < nblk) ? g_part[t] : 0;
    __syncthreads();
#pragma unroll
    for (int off = 1; off < 64; off <<= 1) {
        int tmp = (t < 64 && t >= off) ? sp[t - off] : 0;
        __syncthreads();
        if (t < 64) sp[t] += tmp;
        __syncthreads();
    }
    // sp[] is now INCLUSIVE prefix of chunk partials.

    int base = blockIdx.x * SC_CHUNK + t * SC_PER;
    int v[SC_PER];
    int sum = 0;
#pragma unroll
    for (int j = 0; j < SC_PER; ++j) {
        int i = base + j;
        v[j] = (i < n) ? g_deg[i] : 0;
        sum += v[j];
    }
    s[t] = sum;
    __syncthreads();
#pragma unroll
    for (int off = 1; off < SC_BLK; off <<= 1) {
        int tmp = (t >= off) ? s[t - off] : 0;
        __syncthreads();
        s[t] += tmp;
        __syncthreads();
    }
    int block_total = s[SC_BLK - 1];
    int chunk_prefix = sp[blockIdx.x] - block_total;   // exclusive chunk prefix
    int run = chunk_prefix + s[t] - sum;
#pragma unroll
    for (int j = 0; j < SC_PER; ++j) {
        int i = base + j;
        if (i < n) {
            g_off[i] = run;
            g_cur[i] = run;
            run += v[j];
        }
    }
    if (blockIdx.x == 0 && t == 0) g_off[n] = E;
}

// 4) scatter src ids into CSR slots
__global__ void scatter_kernel(const int* __restrict__ ei, int E) {
    int i = blockIdx.x * blockDim.x + threadIdx.x;
    if (i < E) {
        int src = ei[i];
        int dst = ei[E + i];
        if (dst >= 0 && dst < N_MAX) {
            int pos = atomicAdd(&g_cur[dst], 1);
            if (pos >= 0 && pos < E_MAX) g_csr[pos] = src;
        }
    }
}

// 5) mean aggregation: one warp per node; result stored tf32-rounded
__global__ void agg_kernel(const float* __restrict__ feat, int n) {
    int gwarp = (blockIdx.x * blockDim.x + threadIdx.x) >> 5;
    int lane = threadIdx.x & 31;
    if (gwarp >= n) return;

    int beg = g_off[gwarp];
    int end = g_off[gwarp + 1];
    float4 acc = make_float4(0.f, 0.f, 0.f, 0.f);

    int s_next = (beg < end) ? g_csr[beg] : 0;
    for (int e = beg; e < end; ++e) {
        int s = s_next;
        if (e + 1 < end) s_next = g_csr[e + 1];   // prefetch next index
        float4 v = *(const float4*)&feat[(size_t)s * DIM + lane * 4];
        acc.x += v.x; acc.y += v.y; acc.z += v.z; acc.w += v.w;
    }
    int d = end - beg;
    float scale = 1.0f / (float)(d > 0 ? d : 1);
    float4 o;
    o.x = to_tf32(acc.x * scale);
    o.y = to_tf32(acc.y * scale);
    o.z = to_tf32(acc.z * scale);
    o.w = to_tf32(acc.w * scale);
    *(float4*)&g_agg[(size_t)gwarp * DIM + lane * 4] = o;
}

// ---------------------------------------------------------------------------
// tf32 tensor-core GEMM, software-pipelined (register prefetch of next chunk):
// out[N,128] = [agg | feat](N,256) x g_WT(256,128) + b_l
#define GBM 128
#define GKB 32
#define AS_STRIDE 36   // banks (4g+t): conflict-free A frag loads
#define BS_STRIDE 136  // banks (8t+g): conflict-free B frag loads

__global__ __launch_bounds__(256, 2)
void gemm_tc_kernel(const float* __restrict__ feat,
                    const float* __restrict__ b_l,
                    float* __restrict__ out, int n) {
    __shared__ float As[GBM * AS_STRIDE];   // 128 x 32 (padded)  18.4 KB
    __shared__ float Bs[GKB * BS_STRIDE];   // 32 x 128 (padded)  17.4 KB

    int tid = threadIdx.x;
    int wid = tid >> 5;
    int lane = tid & 31;
    int g = lane >> 2, t = lane & 3;

    int wr = wid & 3;           // warp row: rows wr*32 .. +31
    int wc = wid >> 2;          // warp col: cols wc*64 .. +63
    int block_row = blockIdx.x * GBM;

    // accumulators init with bias
    float acc[2][8][4];
#pragma unroll
    for (int nt = 0; nt < 8; ++nt) {
        int c = wc * 64 + nt * 8 + 2 * t;
        float b0 = b_l[c], b1 = b_l[c + 1];
#pragma unroll
        for (int mt = 0; mt < 2; ++mt) {
            acc[mt][nt][0] = b0; acc[mt][nt][1] = b1;
            acc[mt][nt][2] = b0; acc[mt][nt][3] = b1;
        }
    }

    // tile-load mappings (per thread: 4 float4 for A, 4 float4 for B)
    int a_row = tid >> 3;            // with +64 per i: rows 0..127
    int a_c4 = (tid & 7) * 4;
    int b_row = tid >> 5;            // with +8 per i: rows 0..31
    int b_c4 = (lane) * 4;

    float4 ra[4], rb[4];

    auto load_chunk = [&](int kc) {
        const float* Asrc = (kc < 4) ? g_agg : feat;
        int ksrc = (kc * GKB) & 127;
#pragma unroll
        for (int i = 0; i < 4; ++i) {
            int grow = block_row + a_row + i * 32;
            ra[i] = make_float4(0.f, 0.f, 0.f, 0.f);
            if (grow < n)
                ra[i] = *(const float4*)&Asrc[(size_t)grow * DIM + ksrc + a_c4];
        }
#pragma unroll
        for (int i = 0; i < 4; ++i)
            rb[i] = *(const float4*)&g_WT[(size_t)(kc * GKB + b_row + i * 8) * DIM + b_c4];
    };

    load_chunk(0);

#pragma unroll 1
    for (int kc = 0; kc < 8; ++kc) {
        bool need_cvt = (kc >= 4);   // feat chunks: round to tf32 at STS
#pragma unroll
        for (int i = 0; i < 4; ++i) {
            float* dst = &As[(a_row + i * 32) * AS_STRIDE + a_c4];
            if (need_cvt) {
                dst[0] = to_tf32(ra[i].x); dst[1] = to_tf32(ra[i].y);
                dst[2] = to_tf32(ra[i].z); dst[3] = to_tf32(ra[i].w);
            } else {
                dst[0] = ra[i].x; dst[1] = ra[i].y;
                dst[2] = ra[i].z; dst[3] = ra[i].w;
            }
        }
#pragma unroll
        for (int i = 0; i < 4; ++i)
            *(float4*)&Bs[(b_row + i * 8) * BS_STRIDE + b_c4] = rb[i];
        __syncthreads();

        if (kc < 7) load_chunk(kc + 1);   // overlaps with MMA below

#pragma unroll
        for (int ks = 0; ks < 4; ++ks) {
            int kb = ks * 8;
            uint32_t a[2][4];
#pragma unroll
            for (int mt = 0; mt < 2; ++mt) {
                int rb_ = wr * 32 + mt * 16;
                a[mt][0] = __float_as_uint(As[(rb_ + g) * AS_STRIDE + kb + t]);
                a[mt][1] = __float_as_uint(As[(rb_ + g + 8) * AS_STRIDE + kb + t]);
                a[mt][2] = __float_as_uint(As[(rb_ + g) * AS_STRIDE + kb + t + 4]);
                a[mt][3] = __float_as_uint(As[(rb_ + g + 8) * AS_STRIDE + kb + t + 4]);
            }
#pragma unroll
            for (int nt = 0; nt < 8; ++nt) {
                int cb = wc * 64 + nt * 8 + g;
                uint32_t b0 = __float_as_uint(Bs[(kb + t) * BS_STRIDE + cb]);
                uint32_t b1 = __float_as_uint(Bs[(kb + t + 4) * BS_STRIDE + cb]);
#pragma unroll
                for (int mt = 0; mt < 2; ++mt) {
                    asm volatile(
                        "mma.sync.aligned.m16n8k8.row.col.f32.tf32.tf32.f32 "
                        "{%0,%1,%2,%3}, {%4,%5,%6,%7}, {%8,%9}, {%0,%1,%2,%3};"
                        : "+f"(acc[mt][nt][0]), "+f"(acc[mt][nt][1]),
                          "+f"(acc[mt][nt][2]), "+f"(acc[mt][nt][3])
                        : "r"(a[mt][0]), "r"(a[mt][1]), "r"(a[mt][2]), "r"(a[mt][3]),
                          "r"(b0), "r"(b1));
                }
            }
        }
        __syncthreads();
    }

    // epilogue
#pragma unroll
    for (int mt = 0; mt < 2; ++mt) {
        int r0 = block_row + wr * 32 + mt * 16 + g;
        int r1 = r0 + 8;
#pragma unroll
        for (int nt = 0; nt < 8; ++nt) {
            int c = wc * 64 + nt * 8 + 2 * t;
            if (r0 < n) {
                float2 v = make_float2(acc[mt][nt][0], acc[mt][nt][1]);
                *(float2*)&out[(size_t)r0 * DIM + c] = v;
            }
            if (r1 < n) {
                float2 v = make_float2(acc[mt][nt][2], acc[mt][nt][3]);
                *(float2*)&out[(size_t)r1 * DIM + c] = v;
            }
        }
    }
}

extern "C" void kernel_launch(void* const* d_in, const int* in_sizes, int n_in,
                              void* d_out, int out_size) {
    const float* feature = (const float*)d_in[0];
    const int*   ei      = (const int*)d_in[1];     // int32 (JAX x64 disabled)
    const float* W_l     = (const float*)d_in[2];
    const float* b_l     = (const float*)d_in[3];
    const float* W_r     = (const float*)d_in[4];
    float*       out     = (float*)d_out;

    int N = in_sizes[0] / DIM;
    int E = in_sizes[1] / 2;

    init_kernel<<<(N + 255) / 256, 256>>>(W_l, W_r, N);          // 0
    hist_kernel<<<(E + 255) / 256, 256>>>(ei, E);                // 1

    int nblk = (N + SC_CHUNK - 1) / SC_CHUNK;                    // 49
    part_sum_kernel<<<nblk, SC_BLK>>>(N);                        // 2
    off_kernel<<<nblk, SC_BLK>>>(N, E, nblk);                    // 3
    scatter_kernel<<<(E + 255) / 256, 256>>>(ei, E);             // 4

    int agg_blocks = (N + 7) / 8;
    agg_kernel<<<agg_blocks, 256>>>(feature, N);                 // 5 (ncu slot)

    gemm_tc_kernel<<<(N + GBM - 1) / GBM, 256>>>(feature, b_l, out, N);  // 6
}